// round 7
// baseline (speedup 1.0000x reference)
#include <cuda_runtime.h>
#include <cstdint>

#define N_NODES 100000
#define N_EDGES 1600000
#define DIM 128

// Scratch (all static __device__ — no allocs)
__device__ float g_y[(size_t)N_NODES * DIM];    // y = x @ W^T   (51.2 MB)
__device__ int   g_deg[N_NODES];
__device__ int   g_off[N_NODES + 1];
__device__ int   g_cur[N_NODES];
__device__ int2  g_edge[N_EDGES];               // packed (src, ea bits) per dst-bucket

// ---------------------------------------------------------------------------
// Kernel 1: y = x @ W^T  (R3 form — measured at the SIMT FFMA roofline)
// ---------------------------------------------------------------------------
constexpr int BM = 64;
constexpr int BK = 32;

__global__ __launch_bounds__(256) void gemm_kernel(const float* __restrict__ x,
                                                   const float* __restrict__ W) {
    __shared__ float sX[BM][BK];      // 8 KB
    __shared__ float sWt[BK][DIM];    // 16 KB, sWt[k][o] = W[o][kt+k]

    const int tid = threadIdx.x;
    const int tx  = tid & 31;
    const int ty  = tid >> 5;
    const int row0 = blockIdx.x * BM;

    float acc[8][4];
#pragma unroll
    for (int r = 0; r < 8; r++)
#pragma unroll
        for (int c = 0; c < 4; c++) acc[r][c] = 0.f;

    for (int kt = 0; kt < DIM; kt += BK) {
#pragma unroll
        for (int i = 0; i < 2; i++) {
            int f  = tid + i * 256;
            int r  = f >> 3;
            int k4 = (f & 7) * 4;
            float4 v = make_float4(0.f, 0.f, 0.f, 0.f);
            int grow = row0 + r;
            if (grow < N_NODES)
                v = *(const float4*)(x + (size_t)grow * DIM + kt + k4);
            *(float4*)&sX[r][k4] = v;
        }
#pragma unroll
        for (int i = 0; i < 4; i++) {
            int f  = tid + i * 256;
            int c  = f >> 3;
            int k4 = (f & 7) * 4;
            float4 v = *(const float4*)(W + (size_t)c * DIM + kt + k4);
            sWt[k4 + 0][c] = v.x;
            sWt[k4 + 1][c] = v.y;
            sWt[k4 + 2][c] = v.z;
            sWt[k4 + 3][c] = v.w;
        }
        __syncthreads();

#pragma unroll
        for (int kk = 0; kk < BK; kk++) {
            float4 wv = *(const float4*)&sWt[kk][tx * 4];
#pragma unroll
            for (int r = 0; r < 8; r++) {
                float xv = sX[ty * 8 + r][kk];   // warp-broadcast
                acc[r][0] += xv * wv.x;
                acc[r][1] += xv * wv.y;
                acc[r][2] += xv * wv.z;
                acc[r][3] += xv * wv.w;
            }
        }
        __syncthreads();
    }

#pragma unroll
    for (int r = 0; r < 8; r++) {
        int grow = row0 + ty * 8 + r;
        if (grow < N_NODES) {
            float4 v = make_float4(acc[r][0], acc[r][1], acc[r][2], acc[r][3]);
            *(float4*)(g_y + (size_t)grow * DIM + tx * 4) = v;
        }
    }
}

// ---------------------------------------------------------------------------
// CSR build
// ---------------------------------------------------------------------------
__global__ __launch_bounds__(256) void zero_deg_kernel() {
    int i = blockIdx.x * 256 + threadIdx.x;
    if (i < N_NODES) g_deg[i] = 0;
}

__global__ __launch_bounds__(256) void count_kernel(const int* __restrict__ ei) {
    int e = blockIdx.x * 256 + threadIdx.x;
    if (e < N_EDGES) atomicAdd(&g_deg[__ldg(ei + N_EDGES + e)], 1);
}

// Single-block exclusive scan of g_deg -> g_off (+ copy to g_cur).
__global__ __launch_bounds__(1024) void scan_kernel() {
    __shared__ int ssum[1024];
    const int t  = threadIdx.x;
    const int CH = (N_NODES + 1023) / 1024;   // 98
    const int base = t * CH;

    int s = 0;
    for (int i = 0; i < CH; i++) {
        int idx = base + i;
        if (idx < N_NODES) s += g_deg[idx];
    }
    ssum[t] = s;
    __syncthreads();

    // Hillis-Steele inclusive scan over 1024 partials
    for (int off = 1; off < 1024; off <<= 1) {
        int other = (t >= off) ? ssum[t - off] : 0;
        __syncthreads();
        ssum[t] += other;
        __syncthreads();
    }
    int run = ssum[t] - s;   // exclusive prefix for this thread's chunk

    for (int i = 0; i < CH; i++) {
        int idx = base + i;
        if (idx < N_NODES) {
            g_off[idx] = run;
            g_cur[idx] = run;
            run += g_deg[idx];
        }
    }
    if (t == 1023) g_off[N_NODES] = run;   // = N_EDGES
}

__global__ __launch_bounds__(256) void fill_kernel(const int* __restrict__ ei,
                                                   const float* __restrict__ ea) {
    int e = blockIdx.x * 256 + threadIdx.x;
    if (e >= N_EDGES) return;
    int d   = __ldg(ei + N_EDGES + e);
    int pos = atomicAdd(&g_cur[d], 1);
    g_edge[pos] = make_int2(__ldg(ei + e), __float_as_int(__ldg(ea + e)));
}

// ---------------------------------------------------------------------------
// Gather: one warp per node. out[n] = leaky( sum_e ea_e * y[src_e] + b )
// No atomics; single coalesced write per node. Fuses memset + epilogue.
// ---------------------------------------------------------------------------
__global__ __launch_bounds__(256) void gather_kernel(float* __restrict__ out,
                                                     const float* __restrict__ b) {
    const int n    = (blockIdx.x * 256 + threadIdx.x) >> 5;
    const int lane = threadIdx.x & 31;
    if (n >= N_NODES) return;

    const int beg = __ldg(&g_off[n]);
    const int end = __ldg(&g_off[n + 1]);

    float4 acc = make_float4(0.f, 0.f, 0.f, 0.f);

    int j = beg;
    for (; j + 2 <= end; j += 2) {          // unroll x2 for MLP
        int2 e0 = __ldg(&g_edge[j]);
        int2 e1 = __ldg(&g_edge[j + 1]);
        float4 v0 = *(const float4*)(g_y + (size_t)e0.x * DIM + lane * 4);
        float4 v1 = *(const float4*)(g_y + (size_t)e1.x * DIM + lane * 4);
        float a0 = __int_as_float(e0.y);
        float a1 = __int_as_float(e1.y);
        acc.x += a0 * v0.x; acc.y += a0 * v0.y; acc.z += a0 * v0.z; acc.w += a0 * v0.w;
        acc.x += a1 * v1.x; acc.y += a1 * v1.y; acc.z += a1 * v1.z; acc.w += a1 * v1.w;
    }
    if (j < end) {
        int2 e0 = __ldg(&g_edge[j]);
        float4 v0 = *(const float4*)(g_y + (size_t)e0.x * DIM + lane * 4);
        float a0 = __int_as_float(e0.y);
        acc.x += a0 * v0.x; acc.y += a0 * v0.y; acc.z += a0 * v0.z; acc.w += a0 * v0.w;
    }

    float4 bb = *(const float4*)(b + lane * 4);
    acc.x += bb.x; acc.y += bb.y; acc.z += bb.z; acc.w += bb.w;
    acc.x = acc.x >= 0.f ? acc.x : 0.01f * acc.x;
    acc.y = acc.y >= 0.f ? acc.y : 0.01f * acc.y;
    acc.z = acc.z >= 0.f ? acc.z : 0.01f * acc.z;
    acc.w = acc.w >= 0.f ? acc.w : 0.01f * acc.w;

    *(float4*)(out + (size_t)n * DIM + lane * 4) = acc;
}

// ---------------------------------------------------------------------------
extern "C" void kernel_launch(void* const* d_in, const int* in_sizes, int n_in,
                              void* d_out, int out_size) {
    const float* x  = (const float*)d_in[0];      // [100000, 128] f32
    const int*   ei = (const int*)d_in[1];        // [2, 1600000] i32
    const float* ea = (const float*)d_in[2];      // [1600000] f32
    const float* W  = (const float*)d_in[3];      // [128, 128] f32
    const float* b  = (const float*)d_in[4];      // [128] f32
    float*       out = (float*)d_out;             // [100000, 128] f32

    const int EB = (N_EDGES + 255) / 256;
    const int NB = (N_NODES + 255) / 256;

    // CSR build (independent of gemm)
    zero_deg_kernel<<<NB, 256>>>();
    count_kernel<<<EB, 256>>>(ei);
    scan_kernel<<<1, 1024>>>();
    fill_kernel<<<EB, 256>>>(ei, ea);

    // y = x @ W^T
    gemm_kernel<<<(N_NODES + BM - 1) / BM, 256>>>(x, W);

    // out = leaky( segment_sum(ea * y[src]) + b )
    gather_kernel<<<(N_NODES * 32 + 255) / 256, 256>>>(out, b);
}